// round 1
// baseline (speedup 1.0000x reference)
#include <cuda_runtime.h>

#define D     128
#define NS    50000
#define NDST  50000
#define NE    640000

// ---------------- scratch (static device arrays; no allocation) ----------------
__device__ float    g_hs[NS * D];
__device__ float    g_hd[NDST * D];
__device__ float    g_nf[NDST * D];
__device__ float    g_s[NE];
__device__ float    g_ex[NE];
__device__ float    g_denom[NDST];
__device__ unsigned g_mkey[NDST];

__device__ __forceinline__ float lrelu(float x) { return x > 0.f ? x : 0.01f * x; }

// order-preserving float<->uint encoding for atomicMax
__device__ __forceinline__ unsigned fenc(float f) {
    unsigned u = __float_as_uint(f);
    return (u & 0x80000000u) ? ~u : (u | 0x80000000u);
}
__device__ __forceinline__ float fdec(unsigned u) {
    return __uint_as_float((u & 0x80000000u) ? (u & 0x7FFFFFFFu) : ~u);
}

// ---------------- init: zero accumulators ----------------
__global__ void k_init() {
    int i = blockIdx.x * blockDim.x + threadIdx.x;
    if (i < NDST * D) g_nf[i] = 0.f;
    if (i < NDST) { g_denom[i] = 0.f; g_mkey[i] = 0u; }
}

// ---------------- generic GEMM: C[M,128] = act(A[M,128] @ W[128,128] + bias) ----------------
// block: 256 threads, 128-row tile, 8x8 microtile per thread. W + A tile in SMEM.
#define LDS_STRIDE 132

__global__ __launch_bounds__(256) void k_gemm(
    const float* __restrict__ A, const float* __restrict__ W,
    const float* __restrict__ bias, float* __restrict__ C, int M, int act)
{
    extern __shared__ float sm[];
    float* As = sm;                       // [128][132]
    float* Ws = sm + 128 * LDS_STRIDE;    // [128][132]

    int t  = threadIdx.x;
    int m0 = blockIdx.x * 128;

    // load W (128x128) into SMEM
#pragma unroll
    for (int i = 0; i < 16; i++) {
        int idx = t + i * 256;            // float4 index, 4096 total
        int k = idx >> 5, q = idx & 31;
        float4 v = *(const float4*)(W + k * 128 + q * 4);
        *(float4*)(Ws + k * LDS_STRIDE + q * 4) = v;
    }
    // load A tile (128x128) into SMEM
#pragma unroll
    for (int i = 0; i < 16; i++) {
        int idx = t + i * 256;
        int r = idx >> 5, q = idx & 31;
        int rg = m0 + r;
        float4 v = make_float4(0.f, 0.f, 0.f, 0.f);
        if (rg < M) v = *(const float4*)(A + rg * 128 + q * 4);
        *(float4*)(As + r * LDS_STRIDE + q * 4) = v;
    }
    __syncthreads();

    int tx = t & 15, ty = t >> 4;
    float acc[8][8];
#pragma unroll
    for (int i = 0; i < 8; i++)
#pragma unroll
        for (int j = 0; j < 8; j++) acc[i][j] = 0.f;

#pragma unroll 4
    for (int k = 0; k < 128; k++) {
        float4 b0 = *(float4*)(Ws + k * LDS_STRIDE + tx * 8);
        float4 b1 = *(float4*)(Ws + k * LDS_STRIDE + tx * 8 + 4);
        float bb[8] = {b0.x, b0.y, b0.z, b0.w, b1.x, b1.y, b1.z, b1.w};
        float aa[8];
#pragma unroll
        for (int i = 0; i < 8; i++) aa[i] = As[(ty * 8 + i) * LDS_STRIDE + k];
#pragma unroll
        for (int i = 0; i < 8; i++)
#pragma unroll
            for (int j = 0; j < 8; j++)
                acc[i][j] = fmaf(aa[i], bb[j], acc[i][j]);
    }

    float bj[8];
#pragma unroll
    for (int j = 0; j < 8; j++) bj[j] = __ldg(bias + tx * 8 + j);

#pragma unroll
    for (int i = 0; i < 8; i++) {
        int rg = m0 + ty * 8 + i;
        if (rg < M) {
            float o[8];
#pragma unroll
            for (int j = 0; j < 8; j++) {
                float v = acc[i][j] + bj[j];
                o[j] = act ? lrelu(v) : v;
            }
            *(float4*)(C + rg * 128 + tx * 8)     = make_float4(o[0], o[1], o[2], o[3]);
            *(float4*)(C + rg * 128 + tx * 8 + 4) = make_float4(o[4], o[5], o[6], o[7]);
        }
    }
}

// ---------------- edge score: s[e] = lrelu(lrelu(e)@W_a1 + b_a1) @ W_a2 + b_a2 ----------------
// e = hs[src] + hd[dst] recomputed by L2 gather. 128 edges per block.
__global__ __launch_bounds__(256) void k_edge_score(
    const int* __restrict__ src_idx, const int* __restrict__ dst_idx,
    const float* __restrict__ W_a1, const float* __restrict__ b_a1,
    const float* __restrict__ W_a2, const float* __restrict__ b_a2)
{
    extern __shared__ float sm[];
    float* As = sm;                        // [128][132] : lrelu(e) tile
    float* Ws = sm + 128 * LDS_STRIDE;     // [128][132] : W_a1
    float* sS = sm + 2 * 128 * LDS_STRIDE; // [128]      : per-edge score accum
    __shared__ int sSrc[128], sDst[128];

    int t  = threadIdx.x;
    int e0 = blockIdx.x * 128;

    if (t < 128) {
        sSrc[t] = src_idx[e0 + t];
        sDst[t] = dst_idx[e0 + t];
        sS[t]   = 0.f;
    }
    // load W_a1 (independent of indices)
#pragma unroll
    for (int i = 0; i < 16; i++) {
        int idx = t + i * 256;
        int k = idx >> 5, q = idx & 31;
        float4 v = *(const float4*)(W_a1 + k * 128 + q * 4);
        *(float4*)(Ws + k * LDS_STRIDE + q * 4) = v;
    }
    __syncthreads();

    // gather + build lrelu(e) tile
    const float4* hs4 = (const float4*)g_hs;
    const float4* hd4 = (const float4*)g_hd;
#pragma unroll
    for (int i = 0; i < 16; i++) {
        int idx = t + i * 256;
        int r = idx >> 5, q = idx & 31;
        float4 a = hs4[sSrc[r] * 32 + q];
        float4 b = hd4[sDst[r] * 32 + q];
        float4 v;
        v.x = lrelu(a.x + b.x);
        v.y = lrelu(a.y + b.y);
        v.z = lrelu(a.z + b.z);
        v.w = lrelu(a.w + b.w);
        *(float4*)(As + r * LDS_STRIDE + q * 4) = v;
    }
    __syncthreads();

    int tx = t & 15, ty = t >> 4;
    float acc[8][8];
#pragma unroll
    for (int i = 0; i < 8; i++)
#pragma unroll
        for (int j = 0; j < 8; j++) acc[i][j] = 0.f;

#pragma unroll 4
    for (int k = 0; k < 128; k++) {
        float4 b0 = *(float4*)(Ws + k * LDS_STRIDE + tx * 8);
        float4 b1 = *(float4*)(Ws + k * LDS_STRIDE + tx * 8 + 4);
        float bb[8] = {b0.x, b0.y, b0.z, b0.w, b1.x, b1.y, b1.z, b1.w};
        float aa[8];
#pragma unroll
        for (int i = 0; i < 8; i++) aa[i] = As[(ty * 8 + i) * LDS_STRIDE + k];
#pragma unroll
        for (int i = 0; i < 8; i++)
#pragma unroll
            for (int j = 0; j < 8; j++)
                acc[i][j] = fmaf(aa[i], bb[j], acc[i][j]);
    }

    // fused epilogue: lrelu(v + b_a1) . W_a2, reduced across the 16 col-threads
    float ba1[8], wa2[8];
#pragma unroll
    for (int j = 0; j < 8; j++) {
        ba1[j] = __ldg(b_a1 + tx * 8 + j);
        wa2[j] = __ldg(W_a2 + tx * 8 + j);
    }
#pragma unroll
    for (int i = 0; i < 8; i++) {
        float part = 0.f;
#pragma unroll
        for (int j = 0; j < 8; j++) {
            float v = acc[i][j] + ba1[j];
            part = fmaf(lrelu(v), wa2[j], part);
        }
        atomicAdd(&sS[ty * 8 + i], part);
    }
    __syncthreads();

    if (t < 128) {
        float sv = sS[t] + __ldg(b_a2);
        g_s[e0 + t] = sv;
        atomicMax(&g_mkey[sDst[t]], fenc(sv));
    }
}

// ---------------- exp + denom ----------------
__global__ void k_exp(const int* __restrict__ dst_idx) {
    int e = blockIdx.x * blockDim.x + threadIdx.x;
    if (e >= NE) return;
    int d = dst_idx[e];
    float m  = fdec(g_mkey[d]);
    float ex = expf(g_s[e] - m);
    g_ex[e] = ex;
    atomicAdd(&g_denom[d], ex);
}

// ---------------- aggregation: n_f[dst] += (ex/denom) * e_row ----------------
// one warp per edge; red.global.add.v4.f32 (sm_90+) for 4x fewer L2 atomic ops.
__global__ __launch_bounds__(256) void k_agg(
    const int* __restrict__ src_idx, const int* __restrict__ dst_idx)
{
    int gt   = blockIdx.x * blockDim.x + threadIdx.x;
    int e    = gt >> 5;
    int lane = gt & 31;
    if (e >= NE) return;
    int s = src_idx[e], d = dst_idx[e];
    float w = g_ex[e] / g_denom[d];

    const float4* hs4 = (const float4*)g_hs;
    const float4* hd4 = (const float4*)g_hd;
    float4 a = hs4[s * 32 + lane];
    float4 b = hd4[d * 32 + lane];
    float4 v;
    v.x = w * (a.x + b.x);
    v.y = w * (a.y + b.y);
    v.z = w * (a.z + b.z);
    v.w = w * (a.w + b.w);

    float* p = g_nf + d * 128 + lane * 4;
    asm volatile("red.global.add.v4.f32 [%0], {%1, %2, %3, %4};"
                 :: "l"(p), "f"(v.x), "f"(v.y), "f"(v.z), "f"(v.w) : "memory");
}

// ---------------- launch ----------------
extern "C" void kernel_launch(void* const* d_in, const int* in_sizes, int n_in,
                              void* d_out, int out_size)
{
    const float* feat_src = (const float*)d_in[0];
    const float* feat_dst = (const float*)d_in[1];
    const int*   src_idx  = (const int*)d_in[2];
    const int*   dst_idx  = (const int*)d_in[3];
    const float* W_src    = (const float*)d_in[4];
    const float* b_src    = (const float*)d_in[5];
    const float* W_dst    = (const float*)d_in[6];
    const float* b_dst    = (const float*)d_in[7];
    const float* W_a1     = (const float*)d_in[8];
    const float* b_a1     = (const float*)d_in[9];
    const float* W_a2     = (const float*)d_in[10];
    const float* b_a2     = (const float*)d_in[11];
    const float* W_out    = (const float*)d_in[12];
    const float* b_out    = (const float*)d_in[13];
    float* out = (float*)d_out;

    void *p_hs, *p_hd, *p_nf;
    cudaGetSymbolAddress(&p_hs, g_hs);
    cudaGetSymbolAddress(&p_hd, g_hd);
    cudaGetSymbolAddress(&p_nf, g_nf);

    size_t smem_gemm = (size_t)(2 * 128 * LDS_STRIDE) * sizeof(float);
    size_t smem_edge = smem_gemm + 128 * sizeof(float);
    cudaFuncSetAttribute(k_gemm, cudaFuncAttributeMaxDynamicSharedMemorySize, (int)smem_gemm);
    cudaFuncSetAttribute(k_edge_score, cudaFuncAttributeMaxDynamicSharedMemorySize, (int)smem_edge);

    k_init<<<(NDST * D + 255) / 256, 256>>>();
    k_gemm<<<(NS   + 127) / 128, 256, smem_gemm>>>(feat_src, W_src, b_src, (float*)p_hs, NS,   0);
    k_gemm<<<(NDST + 127) / 128, 256, smem_gemm>>>(feat_dst, W_dst, b_dst, (float*)p_hd, NDST, 0);
    k_edge_score<<<NE / 128, 256, smem_edge>>>(src_idx, dst_idx, W_a1, b_a1, W_a2, b_a2);
    k_exp<<<(NE + 255) / 256, 256>>>(dst_idx);
    k_agg<<<(NE * 32) / 256, 256>>>(src_idx, dst_idx);
    k_gemm<<<(NDST + 127) / 128, 256, smem_gemm>>>((float*)p_nf, W_out, b_out, out, NDST, 1);
}

// round 3
// speedup vs baseline: 1.2786x; 1.2786x over previous
#include <cuda_runtime.h>

#define D     128
#define NS    50000
#define NDST  50000
#define NE    640000

// ---------------- scratch (static device arrays; no allocation) ----------------
__device__ float    g_hs[NS * D];
__device__ float    g_hd[NDST * D];
__device__ float    g_nf[NDST * D];
__device__ float    g_s[NE];
__device__ float    g_ex[NE];
__device__ float    g_denom[NDST];
__device__ unsigned g_mkey[NDST];

__device__ __forceinline__ float lrelu(float x) { return x > 0.f ? x : 0.01f * x; }

// order-preserving float<->uint encoding for atomicMax
__device__ __forceinline__ unsigned fenc(float f) {
    unsigned u = __float_as_uint(f);
    return (u & 0x80000000u) ? ~u : (u | 0x80000000u);
}
__device__ __forceinline__ float fdec(unsigned u) {
    return __uint_as_float((u & 0x80000000u) ? (u & 0x7FFFFFFFu) : ~u);
}

// ---------------- init: zero accumulators ----------------
__global__ void k_init() {
    int i = blockIdx.x * blockDim.x + threadIdx.x;
    if (i < NDST * D) g_nf[i] = 0.f;
    if (i < NDST) { g_denom[i] = 0.f; g_mkey[i] = 0u; }
}

#define LDS_STRIDE 132

// ---------------- GEMM: C[M,128] = act(A[M,128] @ W[128,128] + bias) ----------------
// 512 threads, 256-row tile, 8x8 microtile. smem: A 135KB + W 67.6KB = 203KB (1 CTA, 16 warps).
__global__ __launch_bounds__(512) void k_gemm(
    const float* __restrict__ A, const float* __restrict__ W,
    const float* __restrict__ bias, float* __restrict__ C, int M, int act)
{
    extern __shared__ float sm[];
    float* As = sm;                       // [256][132]
    float* Ws = sm + 256 * LDS_STRIDE;    // [128][132]

    int t  = threadIdx.x;
    int m0 = blockIdx.x * 256;

    // load W (128x128 = 4096 float4)
#pragma unroll
    for (int i = 0; i < 8; i++) {
        int idx = t + i * 512;
        int k = idx >> 5, q = idx & 31;
        float4 v = *(const float4*)(W + k * 128 + q * 4);
        *(float4*)(Ws + k * LDS_STRIDE + q * 4) = v;
    }
    // load A tile (256x128 = 8192 float4)
#pragma unroll
    for (int i = 0; i < 16; i++) {
        int idx = t + i * 512;
        int r = idx >> 5, q = idx & 31;
        int rg = m0 + r;
        float4 v = make_float4(0.f, 0.f, 0.f, 0.f);
        if (rg < M) v = *(const float4*)(A + rg * 128 + q * 4);
        *(float4*)(As + r * LDS_STRIDE + q * 4) = v;
    }
    __syncthreads();

    int tx = t & 15, ty = t >> 4;          // ty: 0..31 (8 rows each), tx: 0..15 (8 cols each)
    float acc[8][8];
#pragma unroll
    for (int i = 0; i < 8; i++)
#pragma unroll
        for (int j = 0; j < 8; j++) acc[i][j] = 0.f;

#pragma unroll 4
    for (int k = 0; k < 128; k++) {
        float4 b0 = *(float4*)(Ws + k * LDS_STRIDE + tx * 8);
        float4 b1 = *(float4*)(Ws + k * LDS_STRIDE + tx * 8 + 4);
        float bb[8] = {b0.x, b0.y, b0.z, b0.w, b1.x, b1.y, b1.z, b1.w};
        float aa[8];
#pragma unroll
        for (int i = 0; i < 8; i++) aa[i] = As[(ty * 8 + i) * LDS_STRIDE + k];
#pragma unroll
        for (int i = 0; i < 8; i++)
#pragma unroll
            for (int j = 0; j < 8; j++)
                acc[i][j] = fmaf(aa[i], bb[j], acc[i][j]);
    }

    float bj[8];
#pragma unroll
    for (int j = 0; j < 8; j++) bj[j] = __ldg(bias + tx * 8 + j);

#pragma unroll
    for (int i = 0; i < 8; i++) {
        int rg = m0 + ty * 8 + i;
        if (rg < M) {
            float o[8];
#pragma unroll
            for (int j = 0; j < 8; j++) {
                float v = acc[i][j] + bj[j];
                o[j] = act ? lrelu(v) : v;
            }
            *(float4*)(C + rg * 128 + tx * 8)     = make_float4(o[0], o[1], o[2], o[3]);
            *(float4*)(C + rg * 128 + tx * 8 + 4) = make_float4(o[4], o[5], o[6], o[7]);
        }
    }
}

// ---------------- edge score: s[e] = lrelu(lrelu(e)@W_a1 + b_a1) @ W_a2 + b_a2 ----------------
// 512 threads, 256-edge tile, 8x8 microtile. Shuffle-reduce epilogue (no shared atomics).
__global__ __launch_bounds__(512) void k_edge_score(
    const int* __restrict__ src_idx, const int* __restrict__ dst_idx,
    const float* __restrict__ W_a1, const float* __restrict__ b_a1,
    const float* __restrict__ W_a2, const float* __restrict__ b_a2)
{
    extern __shared__ float sm[];
    float* As = sm;                        // [256][132] : lrelu(e) tile
    float* Ws = sm + 256 * LDS_STRIDE;     // [128][132] : W_a1
    __shared__ int sSrc[256], sDst[256];

    int t  = threadIdx.x;
    int e0 = blockIdx.x * 256;

    if (t < 256) {
        sSrc[t] = src_idx[e0 + t];
        sDst[t] = dst_idx[e0 + t];
    }
#pragma unroll
    for (int i = 0; i < 8; i++) {
        int idx = t + i * 512;
        int k = idx >> 5, q = idx & 31;
        float4 v = *(const float4*)(W_a1 + k * 128 + q * 4);
        *(float4*)(Ws + k * LDS_STRIDE + q * 4) = v;
    }
    __syncthreads();

    // gather + build lrelu(e) tile (256 x 128)
    const float4* hs4 = (const float4*)g_hs;
    const float4* hd4 = (const float4*)g_hd;
#pragma unroll
    for (int i = 0; i < 16; i++) {
        int idx = t + i * 512;
        int r = idx >> 5, q = idx & 31;
        float4 a = hs4[sSrc[r] * 32 + q];
        float4 b = hd4[sDst[r] * 32 + q];
        float4 v;
        v.x = lrelu(a.x + b.x);
        v.y = lrelu(a.y + b.y);
        v.z = lrelu(a.z + b.z);
        v.w = lrelu(a.w + b.w);
        *(float4*)(As + r * LDS_STRIDE + q * 4) = v;
    }
    __syncthreads();

    int tx = t & 15, ty = t >> 4;
    float acc[8][8];
#pragma unroll
    for (int i = 0; i < 8; i++)
#pragma unroll
        for (int j = 0; j < 8; j++) acc[i][j] = 0.f;

#pragma unroll 4
    for (int k = 0; k < 128; k++) {
        float4 b0 = *(float4*)(Ws + k * LDS_STRIDE + tx * 8);
        float4 b1 = *(float4*)(Ws + k * LDS_STRIDE + tx * 8 + 4);
        float bb[8] = {b0.x, b0.y, b0.z, b0.w, b1.x, b1.y, b1.z, b1.w};
        float aa[8];
#pragma unroll
        for (int i = 0; i < 8; i++) aa[i] = As[(ty * 8 + i) * LDS_STRIDE + k];
#pragma unroll
        for (int i = 0; i < 8; i++)
#pragma unroll
            for (int j = 0; j < 8; j++)
                acc[i][j] = fmaf(aa[i], bb[j], acc[i][j]);
    }

    // epilogue: per-row scalar = sum_j lrelu(acc+b_a1)*W_a2, reduced across the 16 tx lanes
    float ba1[8], wa2[8];
#pragma unroll
    for (int j = 0; j < 8; j++) {
        ba1[j] = __ldg(b_a1 + tx * 8 + j);
        wa2[j] = __ldg(W_a2 + tx * 8 + j);
    }
    float ba2 = __ldg(b_a2);

#pragma unroll
    for (int i = 0; i < 8; i++) {
        float part = 0.f;
#pragma unroll
        for (int j = 0; j < 8; j++) {
            float v = acc[i][j] + ba1[j];
            part = fmaf(lrelu(v), wa2[j], part);
        }
        // reduce across tx (16 lanes of the half-warp)
#pragma unroll
        for (int m = 8; m >= 1; m >>= 1)
            part += __shfl_xor_sync(0xffffffffu, part, m, 16);
        if (tx == 0) {
            int r = ty * 8 + i;
            float sv = part + ba2;
            g_s[e0 + r] = sv;
            atomicMax(&g_mkey[sDst[r]], fenc(sv));
        }
    }
}

// ---------------- exp + denom ----------------
__global__ void k_exp(const int* __restrict__ dst_idx) {
    int e = blockIdx.x * blockDim.x + threadIdx.x;
    if (e >= NE) return;
    int d = dst_idx[e];
    float m  = fdec(g_mkey[d]);
    float ex = expf(g_s[e] - m);
    g_ex[e] = ex;
    atomicAdd(&g_denom[d], ex);
}

// ---------------- aggregation: n_f[dst] += (ex/denom) * e_row ----------------
__global__ __launch_bounds__(256) void k_agg(
    const int* __restrict__ src_idx, const int* __restrict__ dst_idx)
{
    int gt   = blockIdx.x * blockDim.x + threadIdx.x;
    int e    = gt >> 5;
    int lane = gt & 31;
    if (e >= NE) return;
    int s = src_idx[e], d = dst_idx[e];
    float w = g_ex[e] / g_denom[d];

    const float4* hs4 = (const float4*)g_hs;
    const float4* hd4 = (const float4*)g_hd;
    float4 a = hs4[s * 32 + lane];
    float4 b = hd4[d * 32 + lane];
    float4 v;
    v.x = w * (a.x + b.x);
    v.y = w * (a.y + b.y);
    v.z = w * (a.z + b.z);
    v.w = w * (a.w + b.w);

    float* p = g_nf + d * 128 + lane * 4;
    asm volatile("red.global.add.v4.f32 [%0], {%1, %2, %3, %4};"
                 :: "l"(p), "f"(v.x), "f"(v.y), "f"(v.z), "f"(v.w) : "memory");
}

// ---------------- launch ----------------
extern "C" void kernel_launch(void* const* d_in, const int* in_sizes, int n_in,
                              void* d_out, int out_size)
{
    const float* feat_src = (const float*)d_in[0];
    const float* feat_dst = (const float*)d_in[1];
    const int*   src_idx  = (const int*)d_in[2];
    const int*   dst_idx  = (const int*)d_in[3];
    const float* W_src    = (const float*)d_in[4];
    const float* b_src    = (const float*)d_in[5];
    const float* W_dst    = (const float*)d_in[6];
    const float* b_dst    = (const float*)d_in[7];
    const float* W_a1     = (const float*)d_in[8];
    const float* b_a1     = (const float*)d_in[9];
    const float* W_a2     = (const float*)d_in[10];
    const float* b_a2     = (const float*)d_in[11];
    const float* W_out    = (const float*)d_in[12];
    const float* b_out    = (const float*)d_in[13];
    float* out = (float*)d_out;

    void *p_hs, *p_hd, *p_nf;
    cudaGetSymbolAddress(&p_hs, g_hs);
    cudaGetSymbolAddress(&p_hd, g_hd);
    cudaGetSymbolAddress(&p_nf, g_nf);

    size_t smem_big = (size_t)(256 * LDS_STRIDE + 128 * LDS_STRIDE) * sizeof(float); // ~203KB
    cudaFuncSetAttribute(k_gemm,       cudaFuncAttributeMaxDynamicSharedMemorySize, (int)smem_big);
    cudaFuncSetAttribute(k_edge_score, cudaFuncAttributeMaxDynamicSharedMemorySize, (int)smem_big);

    k_init<<<(NDST * D + 255) / 256, 256>>>();
    k_gemm<<<(NS   + 255) / 256, 512, smem_big>>>(feat_src, W_src, b_src, (float*)p_hs, NS,   0);
    k_gemm<<<(NDST + 255) / 256, 512, smem_big>>>(feat_dst, W_dst, b_dst, (float*)p_hd, NDST, 0);
    k_edge_score<<<NE / 256, 512, smem_big>>>(src_idx, dst_idx, W_a1, b_a1, W_a2, b_a2);
    k_exp<<<(NE + 255) / 256, 256>>>(dst_idx);
    k_agg<<<(NE * 32) / 256, 256>>>(src_idx, dst_idx);
    k_gemm<<<(NDST + 255) / 256, 512, smem_big>>>((float*)p_nf, W_out, b_out, out, NDST, 1);
}

// round 5
// speedup vs baseline: 3.5420x; 2.7701x over previous
#include <cuda_runtime.h>
#include <cuda_bf16.h>
#include <cstdint>

#define D     128
#define NS    50000
#define NDST  50000
#define NE    640000

// ---------------- scratch (static device arrays; no allocation) ----------------
__device__ __align__(16) float          g_hs[NS * D];
__device__ __align__(16) float          g_hd[NDST * D];
__device__ __align__(16) float          g_nf[NDST * D];
__device__ float          g_s[NE];
__device__ float          g_ex[NE];
__device__ float          g_denom[NDST];
__device__ unsigned       g_mkey[NDST];
// 4 pre-split transposed weights: [which][n][k], bf16 hi/lo
__device__ __align__(16) __nv_bfloat16  g_whi[4 * D * D];
__device__ __align__(16) __nv_bfloat16  g_wlo[4 * D * D];

__device__ __forceinline__ float lrelu(float x) { return x > 0.f ? x : 0.01f * x; }

__device__ __forceinline__ unsigned fenc(float f) {
    unsigned u = __float_as_uint(f);
    return (u & 0x80000000u) ? ~u : (u | 0x80000000u);
}
__device__ __forceinline__ float fdec(unsigned u) {
    return __uint_as_float((u & 0x80000000u) ? (u & 0x7FFFFFFFu) : ~u);
}

// ---------------- warp-mma helpers (generic PTX: sm_80+) ----------------
__device__ __forceinline__ uint32_t smem_u32(const void* p) {
    return (uint32_t)__cvta_generic_to_shared(p);
}
__device__ __forceinline__ void ldsm4(uint32_t* r, uint32_t addr) {
    asm volatile("ldmatrix.sync.aligned.m8n8.x4.shared.b16 {%0,%1,%2,%3}, [%4];"
                 : "=r"(r[0]), "=r"(r[1]), "=r"(r[2]), "=r"(r[3]) : "r"(addr));
}
__device__ __forceinline__ void ldsm2(uint32_t* r, uint32_t addr) {
    asm volatile("ldmatrix.sync.aligned.m8n8.x2.shared.b16 {%0,%1}, [%2];"
                 : "=r"(r[0]), "=r"(r[1]) : "r"(addr));
}
__device__ __forceinline__ void mma16816(float* c, const uint32_t* a, const uint32_t* b) {
    asm volatile("mma.sync.aligned.m16n8k16.row.col.f32.bf16.bf16.f32 "
                 "{%0,%1,%2,%3}, {%4,%5,%6,%7}, {%8,%9}, {%0,%1,%2,%3};"
                 : "+f"(c[0]), "+f"(c[1]), "+f"(c[2]), "+f"(c[3])
                 : "r"(a[0]), "r"(a[1]), "r"(a[2]), "r"(a[3]), "r"(b[0]), "r"(b[1]));
}
// split two fp32 into packed bf16x2 hi / lo (error compensation)
__device__ __forceinline__ void split2(float x, float y, uint32_t& h, uint32_t& l) {
    __nv_bfloat16 hx = __float2bfloat16(x);
    __nv_bfloat16 hy = __float2bfloat16(y);
    __nv_bfloat16 lx = __float2bfloat16(x - __bfloat162float(hx));
    __nv_bfloat16 ly = __float2bfloat16(y - __bfloat162float(hy));
    h = ((uint32_t)__bfloat16_as_ushort(hy) << 16) | __bfloat16_as_ushort(hx);
    l = ((uint32_t)__bfloat16_as_ushort(ly) << 16) | __bfloat16_as_ushort(lx);
}
// swizzled byte offset of 16B unit (row, colUnit) in a [rows][128 bf16] tile (256B rows)
__device__ __forceinline__ uint32_t uoff(int r, int cu) {
    return (uint32_t)(r * 256 + ((cu ^ (r & 7)) << 4));
}

// smem layout for mma kernels
#define SM_AHI 0
#define SM_ALO 65536
#define SM_BHI 131072
#define SM_BLO 163840
#define SMEM_MMA 196608

// ---------------- init ----------------
__global__ void k_init() {
    int i = blockIdx.x * blockDim.x + threadIdx.x;
    if (i < NDST * D) g_nf[i] = 0.f;
    if (i < NDST) { g_denom[i] = 0.f; g_mkey[i] = 0u; }
}

// ---------------- prep: split W^T into bf16 hi/lo, [n][k] layout ----------------
__global__ void k_split_w(const float* __restrict__ W, int which) {
    int i = blockIdx.x * blockDim.x + threadIdx.x;
    if (i >= D * D) return;
    int n = i >> 7, k = i & 127;
    float w = W[k * D + n];
    __nv_bfloat16 hi = __float2bfloat16(w);
    __nv_bfloat16 lo = __float2bfloat16(w - __bfloat162float(hi));
    g_whi[which * D * D + n * D + k] = hi;
    g_wlo[which * D * D + n * D + k] = lo;
}

// ---------------- dense GEMM via mma.sync: C = act(A @ W + bias) ----------------
// 512 threads, 256-row tile. 3-way bf16 split, fp32 accum.
__global__ __launch_bounds__(512) void k_gemm_mma(
    const float* __restrict__ A,
    const __nv_bfloat16* __restrict__ wh, const __nv_bfloat16* __restrict__ wl,
    const float* __restrict__ bias, float* __restrict__ C, int M, int act)
{
    extern __shared__ char sm[];
    char* Ahi = sm + SM_AHI;
    char* Alo = sm + SM_ALO;
    char* Bhi = sm + SM_BHI;
    char* Blo = sm + SM_BLO;
    __shared__ float sB[128];

    int t  = threadIdx.x;
    int m0 = blockIdx.x * 256;

    if (t < 128) sB[t] = bias[t];

    // stage B (pre-split W^T [n][k]) with swizzle
    for (int i = t; i < 2048; i += 512) {
        int n = i >> 4, cu = i & 15;
        uint4 hv = *(const uint4*)(wh + n * 128 + cu * 8);
        uint4 lv = *(const uint4*)(wl + n * 128 + cu * 8);
        *(uint4*)(Bhi + uoff(n, cu)) = hv;
        *(uint4*)(Blo + uoff(n, cu)) = lv;
    }
    // stage A rows, split to hi/lo
    for (int i = t; i < 4096; i += 512) {
        int r = i >> 4, cu = i & 15;
        int rg = m0 + r;
        float4 a0 = make_float4(0.f, 0.f, 0.f, 0.f), a1 = a0;
        if (rg < M) {
            const float4* ap = (const float4*)(A + rg * 128 + cu * 8);
            a0 = ap[0]; a1 = ap[1];
        }
        uint4 hv, lv;
        split2(a0.x, a0.y, hv.x, lv.x);
        split2(a0.z, a0.w, hv.y, lv.y);
        split2(a1.x, a1.y, hv.z, lv.z);
        split2(a1.z, a1.w, hv.w, lv.w);
        *(uint4*)(Ahi + uoff(r, cu)) = hv;
        *(uint4*)(Alo + uoff(r, cu)) = lv;
    }
    __syncthreads();

    int lane = t & 31, w = t >> 5;
    uint32_t ahiB = smem_u32(Ahi), aloB = smem_u32(Alo);
    uint32_t bhiB = smem_u32(Bhi), bloB = smem_u32(Blo);
    int rowA = w * 16 + (lane & 15);
    uint32_t rbA = (uint32_t)rowA * 256;
    int rxA = lane & 7, cA = (lane >> 4) & 1;
    int nb  = lane & 7, cB = (lane >> 3) & 1;

    int r0 = w * 16 + (lane >> 2);
    int gr0 = m0 + r0, gr1 = gr0 + 8;

#pragma unroll
    for (int h = 0; h < 2; h++) {
        float c[8][4];
#pragma unroll
        for (int n2 = 0; n2 < 8; n2++)
#pragma unroll
            for (int q = 0; q < 4; q++) c[n2][q] = 0.f;

#pragma unroll
        for (int kk = 0; kk < 8; kk++) {
            uint32_t ao = rbA + (uint32_t)((((kk * 2 + cA) ^ rxA)) << 4);
            uint32_t ah[4], al[4];
            ldsm4(ah, ahiB + ao);
            ldsm4(al, aloB + ao);
#pragma unroll
            for (int n2 = 0; n2 < 8; n2++) {
                int nrow = (h * 8 + n2) * 8 + nb;
                uint32_t bo = (uint32_t)(nrow * 256 + (((kk * 2 + cB) ^ nb) << 4));
                uint32_t bh[2], bl[2];
                ldsm2(bh, bhiB + bo);
                ldsm2(bl, bloB + bo);
                mma16816(c[n2], ah, bh);
                mma16816(c[n2], ah, bl);
                mma16816(c[n2], al, bh);
            }
        }
        // store this half's 8 n-tiles
#pragma unroll
        for (int n2 = 0; n2 < 8; n2++) {
            int n0 = (h * 8 + n2) * 8 + (lane & 3) * 2;
            float b0 = sB[n0], b1 = sB[n0 + 1];
            float v00 = c[n2][0] + b0, v01 = c[n2][1] + b1;
            float v10 = c[n2][2] + b0, v11 = c[n2][3] + b1;
            if (act) { v00 = lrelu(v00); v01 = lrelu(v01); v10 = lrelu(v10); v11 = lrelu(v11); }
            if (gr0 < M) *(float2*)(C + gr0 * 128 + n0) = make_float2(v00, v01);
            if (gr1 < M) *(float2*)(C + gr1 * 128 + n0) = make_float2(v10, v11);
        }
    }
}

// ---------------- edge score via mma.sync: 256 edges/CTA ----------------
// s[e] = lrelu(lrelu(e)@W_a1 + b_a1) @ W_a2 + b_a2,  e = hs[src]+hd[dst] (L2 gather)
__global__ __launch_bounds__(512) void k_edge_score(
    const int* __restrict__ src_idx, const int* __restrict__ dst_idx,
    const __nv_bfloat16* __restrict__ wh, const __nv_bfloat16* __restrict__ wl,
    const float* __restrict__ b_a1, const float* __restrict__ W_a2,
    const float* __restrict__ b_a2)
{
    extern __shared__ char sm[];
    char* Ahi = sm + SM_AHI;
    char* Alo = sm + SM_ALO;
    char* Bhi = sm + SM_BHI;
    char* Blo = sm + SM_BLO;
    __shared__ int   sSrc[256], sDst[256];
    __shared__ float sBa1[128], sWa2[128];

    int t  = threadIdx.x;
    int e0 = blockIdx.x * 256;

    if (t < 256) { sSrc[t] = src_idx[e0 + t]; sDst[t] = dst_idx[e0 + t]; }
    if (t < 128) { sBa1[t] = b_a1[t]; sWa2[t] = W_a2[t]; }

    // stage B = pre-split W_a1^T
    for (int i = t; i < 2048; i += 512) {
        int n = i >> 4, cu = i & 15;
        uint4 hv = *(const uint4*)(wh + n * 128 + cu * 8);
        uint4 lv = *(const uint4*)(wl + n * 128 + cu * 8);
        *(uint4*)(Bhi + uoff(n, cu)) = hv;
        *(uint4*)(Blo + uoff(n, cu)) = lv;
    }
    __syncthreads();   // indices visible

    // gather + lrelu + split A tile (256 x 128)
    const float4* hs4 = (const float4*)g_hs;
    const float4* hd4 = (const float4*)g_hd;
    for (int i = t; i < 4096; i += 512) {
        int r = i >> 4, cu = i & 15;
        int si = sSrc[r] * 32 + cu * 2;
        int di = sDst[r] * 32 + cu * 2;
        float4 a0 = hs4[si], a1 = hs4[si + 1];
        float4 b0 = hd4[di], b1 = hd4[di + 1];
        float e0v = lrelu(a0.x + b0.x), e1v = lrelu(a0.y + b0.y);
        float e2v = lrelu(a0.z + b0.z), e3v = lrelu(a0.w + b0.w);
        float e4v = lrelu(a1.x + b1.x), e5v = lrelu(a1.y + b1.y);
        float e6v = lrelu(a1.z + b1.z), e7v = lrelu(a1.w + b1.w);
        uint4 hv, lv;
        split2(e0v, e1v, hv.x, lv.x);
        split2(e2v, e3v, hv.y, lv.y);
        split2(e4v, e5v, hv.z, lv.z);
        split2(e6v, e7v, hv.w, lv.w);
        *(uint4*)(Ahi + uoff(r, cu)) = hv;
        *(uint4*)(Alo + uoff(r, cu)) = lv;
    }
    __syncthreads();

    int lane = t & 31, w = t >> 5;
    uint32_t ahiB = smem_u32(Ahi), aloB = smem_u32(Alo);
    uint32_t bhiB = smem_u32(Bhi), bloB = smem_u32(Blo);
    int rowA = w * 16 + (lane & 15);
    uint32_t rbA = (uint32_t)rowA * 256;
    int rxA = lane & 7, cA = (lane >> 4) & 1;
    int nb  = lane & 7, cB = (lane >> 3) & 1;

    float rs0 = 0.f, rs1 = 0.f;

#pragma unroll
    for (int h = 0; h < 2; h++) {
        float c[8][4];
#pragma unroll
        for (int n2 = 0; n2 < 8; n2++)
#pragma unroll
            for (int q = 0; q < 4; q++) c[n2][q] = 0.f;

#pragma unroll
        for (int kk = 0; kk < 8; kk++) {
            uint32_t ao = rbA + (uint32_t)((((kk * 2 + cA) ^ rxA)) << 4);
            uint32_t ah[4], al[4];
            ldsm4(ah, ahiB + ao);
            ldsm4(al, aloB + ao);
#pragma unroll
            for (int n2 = 0; n2 < 8; n2++) {
                int nrow = (h * 8 + n2) * 8 + nb;
                uint32_t bo = (uint32_t)(nrow * 256 + (((kk * 2 + cB) ^ nb) << 4));
                uint32_t bh[2], bl[2];
                ldsm2(bh, bhiB + bo);
                ldsm2(bl, bloB + bo);
                mma16816(c[n2], ah, bh);
                mma16816(c[n2], ah, bl);
                mma16816(c[n2], al, bh);
            }
        }
        // fold into per-row score partials
#pragma unroll
        for (int n2 = 0; n2 < 8; n2++) {
            int n0 = (h * 8 + n2) * 8 + (lane & 3) * 2;
            float b0 = sBa1[n0], b1 = sBa1[n0 + 1];
            float w0 = sWa2[n0], w1 = sWa2[n0 + 1];
            rs0 += lrelu(c[n2][0] + b0) * w0 + lrelu(c[n2][1] + b1) * w1;
            rs1 += lrelu(c[n2][2] + b0) * w0 + lrelu(c[n2][3] + b1) * w1;
        }
    }

    // reduce across the 4 lanes of each quad
    rs0 += __shfl_xor_sync(0xffffffffu, rs0, 1);
    rs0 += __shfl_xor_sync(0xffffffffu, rs0, 2);
    rs1 += __shfl_xor_sync(0xffffffffu, rs1, 1);
    rs1 += __shfl_xor_sync(0xffffffffu, rs1, 2);

    if ((lane & 3) == 0) {
        int r0 = w * 16 + (lane >> 2);
        int r1 = r0 + 8;
        float ba2 = __ldg(b_a2);
        float s0 = rs0 + ba2, s1 = rs1 + ba2;
        g_s[e0 + r0] = s0;
        g_s[e0 + r1] = s1;
        atomicMax(&g_mkey[sDst[r0]], fenc(s0));
        atomicMax(&g_mkey[sDst[r1]], fenc(s1));
    }
}

// ---------------- exp + denom ----------------
__global__ void k_exp(const int* __restrict__ dst_idx) {
    int e = blockIdx.x * blockDim.x + threadIdx.x;
    if (e >= NE) return;
    int d = dst_idx[e];
    float m  = fdec(g_mkey[d]);
    float ex = expf(g_s[e] - m);
    g_ex[e] = ex;
    atomicAdd(&g_denom[d], ex);
}

// ---------------- aggregation ----------------
__global__ __launch_bounds__(256) void k_agg(
    const int* __restrict__ src_idx, const int* __restrict__ dst_idx)
{
    int gt   = blockIdx.x * blockDim.x + threadIdx.x;
    int e    = gt >> 5;
    int lane = gt & 31;
    if (e >= NE) return;
    int s = src_idx[e], d = dst_idx[e];
    float w = g_ex[e] / g_denom[d];

    const float4* hs4 = (const float4*)g_hs;
    const float4* hd4 = (const float4*)g_hd;
    float4 a = hs4[s * 32 + lane];
    float4 b = hd4[d * 32 + lane];
    float4 v;
    v.x = w * (a.x + b.x);
    v.y = w * (a.y + b.y);
    v.z = w * (a.z + b.z);
    v.w = w * (a.w + b.w);

    float* p = g_nf + d * 128 + lane * 4;
    asm volatile("red.global.add.v4.f32 [%0], {%1, %2, %3, %4};"
                 :: "l"(p), "f"(v.x), "f"(v.y), "f"(v.z), "f"(v.w) : "memory");
}

// ---------------- launch ----------------
extern "C" void kernel_launch(void* const* d_in, const int* in_sizes, int n_in,
                              void* d_out, int out_size)
{
    const float* feat_src = (const float*)d_in[0];
    const float* feat_dst = (const float*)d_in[1];
    const int*   src_idx  = (const int*)d_in[2];
    const int*   dst_idx  = (const int*)d_in[3];
    const float* W_src    = (const float*)d_in[4];
    const float* b_src    = (const float*)d_in[5];
    const float* W_dst    = (const float*)d_in[6];
    const float* b_dst    = (const float*)d_in[7];
    const float* W_a1     = (const float*)d_in[8];
    const float* b_a1     = (const float*)d_in[9];
    const float* W_a2     = (const float*)d_in[10];
    const float* b_a2     = (const float*)d_in[11];
    const float* W_out    = (const float*)d_in[12];
    const float* b_out    = (const float*)d_in[13];
    float* out = (float*)d_out;

    void *p_hs, *p_hd, *p_nf, *p_whi, *p_wlo;
    cudaGetSymbolAddress(&p_hs, g_hs);
    cudaGetSymbolAddress(&p_hd, g_hd);
    cudaGetSymbolAddress(&p_nf, g_nf);
    cudaGetSymbolAddress(&p_whi, g_whi);
    cudaGetSymbolAddress(&p_wlo, g_wlo);
    const __nv_bfloat16* whi = (const __nv_bfloat16*)p_whi;
    const __nv_bfloat16* wlo = (const __nv_bfloat16*)p_wlo;

    cudaFuncSetAttribute(k_gemm_mma,   cudaFuncAttributeMaxDynamicSharedMemorySize, SMEM_MMA);
    cudaFuncSetAttribute(k_edge_score, cudaFuncAttributeMaxDynamicSharedMemorySize, SMEM_MMA);

    k_init<<<(NDST * D + 255) / 256, 256>>>();
    k_split_w<<<64, 256>>>(W_src, 0);
    k_split_w<<<64, 256>>>(W_dst, 1);
    k_split_w<<<64, 256>>>(W_a1,  2);
    k_split_w<<<64, 256>>>(W_out, 3);

    k_gemm_mma<<<(NS + 255) / 256, 512, SMEM_MMA>>>(
        feat_src, whi + 0 * D * D, wlo + 0 * D * D, b_src, (float*)p_hs, NS, 0);
    k_gemm_mma<<<(NDST + 255) / 256, 512, SMEM_MMA>>>(
        feat_dst, whi + 1 * D * D, wlo + 1 * D * D, b_dst, (float*)p_hd, NDST, 0);

    k_edge_score<<<NE / 256, 512, SMEM_MMA>>>(
        src_idx, dst_idx, whi + 2 * D * D, wlo + 2 * D * D, b_a1, W_a2, b_a2);

    k_exp<<<(NE + 255) / 256, 256>>>(dst_idx);
    k_agg<<<(NE * 32) / 256, 256>>>(src_idx, dst_idx);

    k_gemm_mma<<<(NDST + 255) / 256, 512, SMEM_MMA>>>(
        (float*)p_nf, whi + 3 * D * D, wlo + 3 * D * D, b_out, out, NDST, 1);
}

// round 7
// speedup vs baseline: 3.6818x; 1.0395x over previous
#include <cuda_runtime.h>
#include <cuda_bf16.h>
#include <cstdint>

#define D     128
#define NS    50000
#define NDST  50000
#define NE    640000

// ---------------- scratch (static device arrays; no allocation) ----------------
__device__ __align__(16) float          g_hs[NS * D];
__device__ __align__(16) float          g_hd[NDST * D];
__device__ __align__(16) float          g_nf[NDST * D];
__device__ float          g_s[NE];
__device__ float          g_ex[NE];
__device__ float          g_denom[NDST];
__device__ unsigned       g_mkey[NDST];
// 4 pre-split transposed weights: [which][n][k], bf16 hi/lo
__device__ __align__(16) __nv_bfloat16  g_whi[4 * D * D];
__device__ __align__(16) __nv_bfloat16  g_wlo[4 * D * D];

__device__ __forceinline__ float lrelu(float x) { return x > 0.f ? x : 0.01f * x; }

__device__ __forceinline__ unsigned fenc(float f) {
    unsigned u = __float_as_uint(f);
    return (u & 0x80000000u) ? ~u : (u | 0x80000000u);
}
__device__ __forceinline__ float fdec(unsigned u) {
    return __uint_as_float((u & 0x80000000u) ? (u & 0x7FFFFFFFu) : ~u);
}

// ---------------- warp-mma helpers (generic PTX: sm_80+) ----------------
__device__ __forceinline__ uint32_t smem_u32(const void* p) {
    return (uint32_t)__cvta_generic_to_shared(p);
}
__device__ __forceinline__ void ldsm4(uint32_t* r, uint32_t addr) {
    asm volatile("ldmatrix.sync.aligned.m8n8.x4.shared.b16 {%0,%1,%2,%3}, [%4];"
                 : "=r"(r[0]), "=r"(r[1]), "=r"(r[2]), "=r"(r[3]) : "r"(addr));
}
__device__ __forceinline__ void mma16816(float* c, const uint32_t* a, const uint32_t* b) {
    asm volatile("mma.sync.aligned.m16n8k16.row.col.f32.bf16.bf16.f32 "
                 "{%0,%1,%2,%3}, {%4,%5,%6,%7}, {%8,%9}, {%0,%1,%2,%3};"
                 : "+f"(c[0]), "+f"(c[1]), "+f"(c[2]), "+f"(c[3])
                 : "r"(a[0]), "r"(a[1]), "r"(a[2]), "r"(a[3]), "r"(b[0]), "r"(b[1]));
}
// split two fp32 into packed bf16x2 hi / lo (error compensation)
__device__ __forceinline__ void split2(float x, float y, uint32_t& h, uint32_t& l) {
    __nv_bfloat16 hx = __float2bfloat16(x);
    __nv_bfloat16 hy = __float2bfloat16(y);
    __nv_bfloat16 lx = __float2bfloat16(x - __bfloat162float(hx));
    __nv_bfloat16 ly = __float2bfloat16(y - __bfloat162float(hy));
    h = ((uint32_t)__bfloat16_as_ushort(hy) << 16) | __bfloat16_as_ushort(hx);
    l = ((uint32_t)__bfloat16_as_ushort(ly) << 16) | __bfloat16_as_ushort(lx);
}
// swizzled byte offset of 16B unit (row, colUnit) in a [rows][128 bf16] tile (256B rows)
__device__ __forceinline__ uint32_t uoff(int r, int cu) {
    return (uint32_t)(r * 256 + ((cu ^ (r & 7)) << 4));
}

// smem layout for mma kernels
#define SM_AHI 0
#define SM_ALO 65536
#define SM_BHI 131072
#define SM_BLO 163840
#define SMEM_MMA 196608

// ---------------- init (two tiny kernels; also aligns profiler skip) ----------------
__global__ void k_init_nf() {
    int i = blockIdx.x * blockDim.x + threadIdx.x;
    if (i < NDST * D) g_nf[i] = 0.f;
}
__global__ void k_init_seg() {
    int i = blockIdx.x * blockDim.x + threadIdx.x;
    if (i < NDST) { g_denom[i] = 0.f; g_mkey[i] = 0u; }
}

// ---------------- prep: split all 4 W^T into bf16 hi/lo, [n][k] layout ----------------
__global__ void k_prep(const float* __restrict__ W0, const float* __restrict__ W1,
                       const float* __restrict__ W2, const float* __restrict__ W3)
{
    int i = blockIdx.x * blockDim.x + threadIdx.x;
    if (i >= 4 * D * D) return;
    int which = i >> 14;
    int j = i & (D * D - 1);
    int n = j >> 7, k = j & 127;
    const float* W = which == 0 ? W0 : which == 1 ? W1 : which == 2 ? W2 : W3;
    float w = W[k * D + n];
    __nv_bfloat16 hi = __float2bfloat16(w);
    __nv_bfloat16 lo = __float2bfloat16(w - __bfloat162float(hi));
    g_whi[i] = hi;
    g_wlo[i] = lo;
}

// ---------------- dense GEMM via mma.sync: C = act(A (+gate?A2) @ W + bias) ----------------
__global__ __launch_bounds__(512) void k_gemm_mma(
    const float* __restrict__ A, const float* __restrict__ A2,
    const float* __restrict__ gate,
    const __nv_bfloat16* __restrict__ wh, const __nv_bfloat16* __restrict__ wl,
    const float* __restrict__ bias, float* __restrict__ C, int M, int act)
{
    extern __shared__ char sm[];
    char* Ahi = sm + SM_AHI;
    char* Alo = sm + SM_ALO;
    char* Bhi = sm + SM_BHI;
    char* Blo = sm + SM_BLO;
    __shared__ float sB[128];

    int t  = threadIdx.x;
    int m0 = blockIdx.x * 256;

    if (t < 128) sB[t] = bias[t];

    // stage B (pre-split W^T [n][k]) with swizzle
    for (int i = t; i < 2048; i += 512) {
        int n = i >> 4, cu = i & 15;
        uint4 hv = *(const uint4*)(wh + n * 128 + cu * 8);
        uint4 lv = *(const uint4*)(wl + n * 128 + cu * 8);
        *(uint4*)(Bhi + uoff(n, cu)) = hv;
        *(uint4*)(Blo + uoff(n, cu)) = lv;
    }
    // stage A rows (+ optional gated A2), split to hi/lo
    for (int i = t; i < 4096; i += 512) {
        int r = i >> 4, cu = i & 15;
        int rg = m0 + r;
        float4 a0 = make_float4(0.f, 0.f, 0.f, 0.f), a1 = a0;
        if (rg < M) {
            const float4* ap = (const float4*)(A + rg * 128 + cu * 8);
            a0 = ap[0]; a1 = ap[1];
            if (A2 && gate[rg] > 0.f) {
                const float4* bp = (const float4*)(A2 + rg * 128 + cu * 8);
                float4 b0 = bp[0], b1 = bp[1];
                a0.x += b0.x; a0.y += b0.y; a0.z += b0.z; a0.w += b0.w;
                a1.x += b1.x; a1.y += b1.y; a1.z += b1.z; a1.w += b1.w;
            }
        }
        uint4 hv, lv;
        split2(a0.x, a0.y, hv.x, lv.x);
        split2(a0.z, a0.w, hv.y, lv.y);
        split2(a1.x, a1.y, hv.z, lv.z);
        split2(a1.z, a1.w, hv.w, lv.w);
        *(uint4*)(Ahi + uoff(r, cu)) = hv;
        *(uint4*)(Alo + uoff(r, cu)) = lv;
    }
    __syncthreads();

    int lane = t & 31, w = t >> 5;
    uint32_t ahiB = smem_u32(Ahi), aloB = smem_u32(Alo);
    uint32_t bhiB = smem_u32(Bhi), bloB = smem_u32(Blo);
    int rowA = w * 16 + (lane & 15);
    uint32_t rbA = (uint32_t)rowA * 256;
    int rxA = lane & 7, cA = (lane >> 4) & 1;
    // B ldsm4 addressing: lanes 0-15 -> n-rows 0-7 (k-lo / k-hi), lanes 16-31 -> n-rows 8-15
    int rBoff = ((lane >> 4) << 3) + (lane & 7);
    int cB2   = (lane >> 3) & 1;
    int rxB   = lane & 7;

    int r0 = w * 16 + (lane >> 2);
    int gr0 = m0 + r0, gr1 = gr0 + 8;

#pragma unroll
    for (int h = 0; h < 2; h++) {
        float c[8][4];
#pragma unroll
        for (int n2 = 0; n2 < 8; n2++)
#pragma unroll
            for (int q = 0; q < 4; q++) c[n2][q] = 0.f;

#pragma unroll
        for (int kk = 0; kk < 8; kk++) {
            uint32_t ao = rbA + (uint32_t)((((kk * 2 + cA) ^ rxA)) << 4);
            uint32_t ah[4], al[4];
            ldsm4(ah, ahiB + ao);
            ldsm4(al, aloB + ao);
#pragma unroll
            for (int p = 0; p < 4; p++) {
                int rowB = h * 64 + p * 16 + rBoff;
                uint32_t bo = (uint32_t)(rowB * 256 + (((kk * 2 + cB2) ^ rxB) << 4));
                uint32_t bh[4], bl[4];
                ldsm4(bh, bhiB + bo);
                ldsm4(bl, bloB + bo);
                mma16816(c[2 * p],     ah, bh);
                mma16816(c[2 * p + 1], ah, bh + 2);
                mma16816(c[2 * p],     ah, bl);
                mma16816(c[2 * p + 1], ah, bl + 2);
                mma16816(c[2 * p],     al, bh);
                mma16816(c[2 * p + 1], al, bh + 2);
            }
        }
#pragma unroll
        for (int n2 = 0; n2 < 8; n2++) {
            int n0 = (h * 8 + n2) * 8 + (lane & 3) * 2;
            float b0 = sB[n0], b1 = sB[n0 + 1];
            float v00 = c[n2][0] + b0, v01 = c[n2][1] + b1;
            float v10 = c[n2][2] + b0, v11 = c[n2][3] + b1;
            if (act) { v00 = lrelu(v00); v01 = lrelu(v01); v10 = lrelu(v10); v11 = lrelu(v11); }
            if (gr0 < M) *(float2*)(C + gr0 * 128 + n0) = make_float2(v00, v01);
            if (gr1 < M) *(float2*)(C + gr1 * 128 + n0) = make_float2(v10, v11);
        }
    }
}

// ---------------- edge score via mma.sync: 256 edges/CTA ----------------
__global__ __launch_bounds__(512) void k_edge_score(
    const int* __restrict__ src_idx, const int* __restrict__ dst_idx,
    const __nv_bfloat16* __restrict__ wh, const __nv_bfloat16* __restrict__ wl,
    const float* __restrict__ b_a1, const float* __restrict__ W_a2,
    const float* __restrict__ b_a2)
{
    extern __shared__ char sm[];
    char* Ahi = sm + SM_AHI;
    char* Alo = sm + SM_ALO;
    char* Bhi = sm + SM_BHI;
    char* Blo = sm + SM_BLO;
    __shared__ int   sSrc[256], sDst[256];
    __shared__ float sBa1[128], sWa2[128];

    int t  = threadIdx.x;
    int e0 = blockIdx.x * 256;

    if (t < 256) { sSrc[t] = src_idx[e0 + t]; sDst[t] = dst_idx[e0 + t]; }
    if (t < 128) { sBa1[t] = b_a1[t]; sWa2[t] = W_a2[t]; }

    for (int i = t; i < 2048; i += 512) {
        int n = i >> 4, cu = i & 15;
        uint4 hv = *(const uint4*)(wh + n * 128 + cu * 8);
        uint4 lv = *(const uint4*)(wl + n * 128 + cu * 8);
        *(uint4*)(Bhi + uoff(n, cu)) = hv;
        *(uint4*)(Blo + uoff(n, cu)) = lv;
    }
    __syncthreads();

    const float4* hs4 = (const float4*)g_hs;
    const float4* hd4 = (const float4*)g_hd;
    for (int i = t; i < 4096; i += 512) {
        int r = i >> 4, cu = i & 15;
        int si = sSrc[r] * 32 + cu * 2;
        int di = sDst[r] * 32 + cu * 2;
        float4 a0 = hs4[si], a1 = hs4[si + 1];
        float4 b0 = hd4[di], b1 = hd4[di + 1];
        float e0v = lrelu(a0.x + b0.x), e1v = lrelu(a0.y + b0.y);
        float e2v = lrelu(a0.z + b0.z), e3v = lrelu(a0.w + b0.w);
        float e4v = lrelu(a1.x + b1.x), e5v = lrelu(a1.y + b1.y);
        float e6v = lrelu(a1.z + b1.z), e7v = lrelu(a1.w + b1.w);
        uint4 hv, lv;
        split2(e0v, e1v, hv.x, lv.x);
        split2(e2v, e3v, hv.y, lv.y);
        split2(e4v, e5v, hv.z, lv.z);
        split2(e6v, e7v, hv.w, lv.w);
        *(uint4*)(Ahi + uoff(r, cu)) = hv;
        *(uint4*)(Alo + uoff(r, cu)) = lv;
    }
    __syncthreads();

    int lane = t & 31, w = t >> 5;
    uint32_t ahiB = smem_u32(Ahi), aloB = smem_u32(Alo);
    uint32_t bhiB = smem_u32(Bhi), bloB = smem_u32(Blo);
    int rowA = w * 16 + (lane & 15);
    uint32_t rbA = (uint32_t)rowA * 256;
    int rxA = lane & 7, cA = (lane >> 4) & 1;
    int rBoff = ((lane >> 4) << 3) + (lane & 7);
    int cB2   = (lane >> 3) & 1;
    int rxB   = lane & 7;

    float rs0 = 0.f, rs1 = 0.f;

#pragma unroll
    for (int h = 0; h < 2; h++) {
        float c[8][4];
#pragma unroll
        for (int n2 = 0; n2 < 8; n2++)
#pragma unroll
            for (int q = 0; q < 4; q++) c[n2][q] = 0.f;

#pragma unroll
        for (int kk = 0; kk < 8; kk++) {
            uint32_t ao = rbA + (uint32_t)((((kk * 2 + cA) ^ rxA)) << 4);
            uint32_t ah[4], al[4];
            ldsm4(ah, ahiB + ao);
            ldsm4(al, aloB + ao);
#pragma unroll
            for (int p = 0; p < 4; p++) {
                int rowB = h * 64 + p * 16 + rBoff;
                uint32_t bo = (uint32_t)(rowB * 256 + (((kk * 2 + cB2) ^ rxB) << 4));
                uint32_t bh[4], bl[4];
                ldsm4(bh, bhiB + bo);
                ldsm4(bl, bloB + bo);
                mma16816(c[2 * p],     ah, bh);
                mma16816(c[2 * p + 1], ah, bh + 2);
                mma16816(c[2 * p],     ah, bl);
                mma16816(c[2 * p + 1], ah, bl + 2);
                mma16816(c[2 * p],     al, bh);
                mma16816(c[2 * p + 1], al, bh + 2);
            }
        }
#pragma unroll
        for (int n2 = 0; n2 < 8; n2++) {
            int n0 = (h * 8 + n2) * 8 + (lane & 3) * 2;
            float b0 = sBa1[n0], b1 = sBa1[n0 + 1];
            float w0 = sWa2[n0], w1 = sWa2[n0 + 1];
            rs0 += lrelu(c[n2][0] + b0) * w0 + lrelu(c[n2][1] + b1) * w1;
            rs1 += lrelu(c[n2][2] + b0) * w0 + lrelu(c[n2][3] + b1) * w1;
        }
    }

    rs0 += __shfl_xor_sync(0xffffffffu, rs0, 1);
    rs0 += __shfl_xor_sync(0xffffffffu, rs0, 2);
    rs1 += __shfl_xor_sync(0xffffffffu, rs1, 1);
    rs1 += __shfl_xor_sync(0xffffffffu, rs1, 2);

    if ((lane & 3) == 0) {
        int r0 = w * 16 + (lane >> 2);
        int r1 = r0 + 8;
        float ba2 = __ldg(b_a2);
        float s0 = rs0 + ba2, s1 = rs1 + ba2;
        g_s[e0 + r0] = s0;
        g_s[e0 + r1] = s1;
        atomicMax(&g_mkey[sDst[r0]], fenc(s0));
        atomicMax(&g_mkey[sDst[r1]], fenc(s1));
    }
}

// ---------------- exp + denom ----------------
__global__ void k_exp(const int* __restrict__ dst_idx) {
    int e = blockIdx.x * blockDim.x + threadIdx.x;
    if (e >= NE) return;
    int d = dst_idx[e];
    float m  = fdec(g_mkey[d]);
    float ex = expf(g_s[e] - m);
    g_ex[e] = ex;
    atomicAdd(&g_denom[d], ex);
}

// ---------------- aggregation: n_f[dst] += alpha * hs[src]  (hd term added in final GEMM) ----------------
__global__ __launch_bounds__(256) void k_agg(
    const int* __restrict__ src_idx, const int* __restrict__ dst_idx)
{
    int gt   = blockIdx.x * blockDim.x + threadIdx.x;
    int e    = gt >> 5;
    int lane = gt & 31;
    if (e >= NE) return;
    int s = src_idx[e], d = dst_idx[e];
    float w = g_ex[e] / g_denom[d];

    const float4* hs4 = (const float4*)g_hs;
    float4 a = hs4[s * 32 + lane];
    float4 v = make_float4(w * a.x, w * a.y, w * a.z, w * a.w);

    float* p = g_nf + d * 128 + lane * 4;
    asm volatile("red.global.add.v4.f32 [%0], {%1, %2, %3, %4};"
                 :: "l"(p), "f"(v.x), "f"(v.y), "f"(v.z), "f"(v.w) : "memory");
}

// ---------------- launch ----------------
extern "C" void kernel_launch(void* const* d_in, const int* in_sizes, int n_in,
                              void* d_out, int out_size)
{
    const float* feat_src = (const float*)d_in[0];
    const float* feat_dst = (const float*)d_in[1];
    const int*   src_idx  = (const int*)d_in[2];
    const int*   dst_idx  = (const int*)d_in[3];
    const float* W_src    = (const float*)d_in[4];
    const float* b_src    = (const float*)d_in[5];
    const float* W_dst    = (const float*)d_in[6];
    const float* b_dst    = (const float*)d_in[7];
    const float* W_a1     = (const float*)d_in[8];
    const float* b_a1     = (const float*)d_in[9];
    const float* W_a2     = (const float*)d_in[10];
    const float* b_a2     = (const float*)d_in[11];
    const float* W_out    = (const float*)d_in[12];
    const float* b_out    = (const float*)d_in[13];
    float* out = (float*)d_out;

    void *p_hs, *p_hd, *p_nf, *p_whi, *p_wlo, *p_den;
    cudaGetSymbolAddress(&p_hs, g_hs);
    cudaGetSymbolAddress(&p_hd, g_hd);
    cudaGetSymbolAddress(&p_nf, g_nf);
    cudaGetSymbolAddress(&p_whi, g_whi);
    cudaGetSymbolAddress(&p_wlo, g_wlo);
    cudaGetSymbolAddress(&p_den, g_denom);
    const __nv_bfloat16* whi = (const __nv_bfloat16*)p_whi;
    const __nv_bfloat16* wlo = (const __nv_bfloat16*)p_wlo;

    cudaFuncSetAttribute(k_gemm_mma,   cudaFuncAttributeMaxDynamicSharedMemorySize, SMEM_MMA);
    cudaFuncSetAttribute(k_edge_score, cudaFuncAttributeMaxDynamicSharedMemorySize, SMEM_MMA);

    k_init_nf<<<(NDST * D + 255) / 256, 256>>>();                          // 0
    k_init_seg<<<(NDST + 255) / 256, 256>>>();                             // 1
    k_prep<<<(4 * D * D + 255) / 256, 256>>>(W_src, W_dst, W_a1, W_out);   // 2

    k_gemm_mma<<<(NS + 255) / 256, 512, SMEM_MMA>>>(                       // 3
        feat_src, nullptr, nullptr, whi + 0 * D * D, wlo + 0 * D * D, b_src, (float*)p_hs, NS, 0);
    k_gemm_mma<<<(NDST + 255) / 256, 512, SMEM_MMA>>>(                     // 4
        feat_dst, nullptr, nullptr, whi + 1 * D * D, wlo + 1 * D * D, b_dst, (float*)p_hd, NDST, 0);

    k_edge_score<<<NE / 256, 512, SMEM_MMA>>>(                             // 5 (profiled)
        src_idx, dst_idx, whi + 2 * D * D, wlo + 2 * D * D, b_a1, W_a2, b_a2);

    k_exp<<<(NE + 255) / 256, 256>>>(dst_idx);                             // 6
    k_agg<<<(NE * 32) / 256, 256>>>(src_idx, dst_idx);                     // 7

    k_gemm_mma<<<(NDST + 255) / 256, 512, SMEM_MMA>>>(                     // 8
        (float*)p_nf, (const float*)p_hd, (const float*)p_den,
        whi + 3 * D * D, wlo + 3 * D * D, b_out, out, NDST, 1);
}